// round 17
// baseline (speedup 1.0000x reference)
#include <cuda_runtime.h>
#include <cuda_fp16.h>
#include <cstdint>
#include <cstddef>

// Problem dims
#define Bq 1024
#define Sq 200
#define Hq 256
#define Eq 128
#define Vq 100000

// ---------------- scratch (__device__ globals) ---------------------------------
__device__ __half g_enc_h[(size_t)Sq * Bq * Hq];   // zero-init; only unmasked
                                                   // rows ever written
__device__ __half g_Wout_h[(size_t)Vq * Hq];
__device__ __half g_WaTtop_h[Hq * Hq];
__device__ __half g_WaTbot_h[Hq * Hq];
__device__ __half g_h_h[Bq * Hq];
__device__ __half g_Wih_h[3 * Hq * (Eq + Hq)];
__device__ __half g_Whh_h[3 * Hq * Hq];
__device__ __half g_rnnin_h[Bq * (Eq + Hq)];
__device__ __half g_hnew_h[Bq * Hq];
__device__ float  g_hWa[Bq * Hq];
__device__ float  g_att[Bq * Sq];
__device__ float  g_gi[Bq * 3 * Hq];
__device__ float  g_gh[Bq * 3 * Hq];
__device__ int    g_idx[Sq * Bq];
__device__ int    g_cnt[4];
__device__ int    g_flag;

// ---------------- helpers ------------------------------------------------------
__device__ __forceinline__ uint32_t f2h2(float x, float y) {
    __half2 h = __floats2half2_rn(x, y);
    return *(uint32_t*)&h;
}

__device__ __forceinline__ uint32_t smem_u32(const void* p) {
    uint32_t a;
    asm("{ .reg .u64 t; cvta.to.shared.u64 t, %1; cvt.u32.u64 %0, t; }"
        : "=r"(a) : "l"(p));
    return a;
}

__device__ __forceinline__ void mma_fp16(float* c,
                                         uint32_t a0, uint32_t a1, uint32_t a2, uint32_t a3,
                                         uint32_t b0, uint32_t b1) {
    asm volatile(
        "mma.sync.aligned.m16n8k16.row.col.f32.f16.f16.f32 "
        "{%0,%1,%2,%3}, {%4,%5,%6,%7}, {%8,%9}, {%0,%1,%2,%3};\n"
        : "+f"(c[0]), "+f"(c[1]), "+f"(c[2]), "+f"(c[3])
        : "r"(a0), "r"(a1), "r"(a2), "r"(a3), "r"(b0), "r"(b1));
}

#define LDMX4(r0, r1, r2, r3, a)                                                \
    asm volatile("ldmatrix.sync.aligned.m8n8.x4.shared.b16 {%0,%1,%2,%3}, [%4];" \
                 : "=r"(r0), "=r"(r1), "=r"(r2), "=r"(r3) : "r"(a))

#define CPA16(dst, src, pred)                                                   \
    asm volatile("cp.async.cg.shared.global [%0], [%1], 16, %2;"                \
                 :: "r"(dst), "l"(src), "r"((pred) ? 16 : 0) : "memory")
#define CPA_COMMIT() asm volatile("cp.async.commit_group;" ::: "memory")
#define CPA_WAIT1()  asm volatile("cp.async.wait_group 1;" ::: "memory")
#define CPA_WAIT3()  asm volatile("cp.async.wait_group 3;" ::: "memory")

// ---------------- generic fp16 NT GEMM -----------------------------------------
// C[M,N] = A[M,K] @ B[N,K]^T (+bias | +=C). fp16 in, fp32 acc/out.
// 128x256 block, 8 warps 64x64, K-chunk 32, 5-stage cp.async, 80 B row stride.
// lda/ldb: row strides (elements). accm!=0: accumulate into existing C.
#define ST_A 10240
#define ST_B 20480
#define STG_SZ (ST_A + ST_B)
#define NSTAGE 5
#define GTOT (NSTAGE * STG_SZ)     // 153600

__global__ __launch_bounds__(256, 1)
void mma_gemm(const __half* __restrict__ A, const __half* __restrict__ Bm,
              const float* __restrict__ bias, float* __restrict__ C,
              int M, int N, int K, int lda, int ldb, int accm) {
    extern __shared__ char smem[];
    const uint32_t sbase = smem_u32(smem);

    const int tid  = threadIdx.x;
    const int lane = tid & 31;
    const int warp = tid >> 5;
    const int wm = (warp >> 2) * 64;
    const int wn = (warp & 3) * 64;
    const int bm = blockIdx.x * 128;
    const int bn = blockIdx.y * 256;
    const int lq = lane >> 2;
    const int lr = lane & 3;

    const int rin = lane & 7;
    uint32_t a_l[4], b_l[4];
    {
        const int r8   = (lane >> 3) & 1;
        const int kh_a = (lane >> 4) & 1;
        const int n8   = (lane >> 4) & 1;
        const int kh_b = (lane >> 3) & 1;
#pragma unroll
        for (int mf = 0; mf < 4; mf++)
            a_l[mf] = (uint32_t)((wm + mf * 16 + r8 * 8 + rin) * 80 + kh_a * 16);
#pragma unroll
        for (int p2 = 0; p2 < 4; p2++)
            b_l[p2] = (uint32_t)((wn + p2 * 16 + n8 * 8 + rin) * 80 + kh_b * 16);
    }

    float acc[4][8][4];
#pragma unroll
    for (int i = 0; i < 4; i++)
#pragma unroll
        for (int j = 0; j < 8; j++)
#pragma unroll
            for (int k = 0; k < 4; k++) acc[i][j][k] = 0.0f;

    const int nch = K / 32;

#define ISSUE(c)                                                            \
    do {                                                                    \
        const int kc = (c) * 32;                                            \
        const uint32_t sa0 = sbase + ((c) % NSTAGE) * STG_SZ;               \
        const uint32_t sb0 = sa0 + ST_A;                                    \
        _Pragma("unroll")                                                   \
        for (int l = 0; l < 2; l++) {                                       \
            int q = tid + l * 256;                                          \
            int row = q >> 2, seg = q & 3;                                  \
            CPA16(sa0 + row * 80 + seg * 16,                                \
                  A + (size_t)(bm + row) * lda + kc + seg * 8, true);       \
        }                                                                   \
        _Pragma("unroll")                                                   \
        for (int l = 0; l < 4; l++) {                                       \
            int q = tid + l * 256;                                          \
            int row = q >> 2, seg = q & 3;                                  \
            CPA16(sb0 + row * 80 + seg * 16,                                \
                  Bm + (size_t)(bn + row) * ldb + kc + seg * 8,             \
                  (bn + row) < N);                                          \
        }                                                                   \
    } while (0)

#pragma unroll
    for (int i = 0; i < 4; i++) {
        if (i < nch) ISSUE(i);
        CPA_COMMIT();
    }

    for (int c = 0; c < nch; c++) {
        CPA_WAIT3();
        __syncthreads();
        if (c + 4 < nch) ISSUE(c + 4);
        CPA_COMMIT();

        const uint32_t aA = sbase + (c % NSTAGE) * STG_SZ;
        const uint32_t aB = aA + ST_A;

#pragma unroll
        for (int ks = 0; ks < 2; ks++) {
            uint32_t bf[8][2];
#pragma unroll
            for (int p2 = 0; p2 < 4; p2++)
                LDMX4(bf[2 * p2][0], bf[2 * p2][1], bf[2 * p2 + 1][0], bf[2 * p2 + 1][1],
                      aB + b_l[p2] + ks * 32);
#pragma unroll
            for (int mf = 0; mf < 4; mf++) {
                uint32_t a0, a1, a2, a3;
                LDMX4(a0, a1, a2, a3, aA + a_l[mf] + ks * 32);
#pragma unroll
                for (int nf = 0; nf < 8; nf++)
                    mma_fp16(acc[mf][nf], a0, a1, a2, a3, bf[nf][0], bf[nf][1]);
            }
        }
    }
#undef ISSUE

#pragma unroll
    for (int mf = 0; mf < 4; mf++) {
        int r0 = bm + wm + mf * 16 + lq;
#pragma unroll
        for (int nf = 0; nf < 8; nf++) {
            int col = bn + wn + nf * 8 + lr * 2;
            if (col < N) {
                float b0 = bias ? bias[col] : 0.0f;
                float b1 = bias ? bias[col + 1] : 0.0f;
                float2 v0 = make_float2(acc[mf][nf][0] + b0, acc[mf][nf][1] + b1);
                float2 v1 = make_float2(acc[mf][nf][2] + b0, acc[mf][nf][3] + b1);
                float* p0 = C + (size_t)r0 * N + col;
                float* p1 = C + (size_t)(r0 + 8) * N + col;
                if (accm) {
                    float2 o0 = *(float2*)p0, o1 = *(float2*)p1;
                    v0.x += o0.x; v0.y += o0.y; v1.x += o1.x; v1.y += o1.y;
                }
                *(float2*)p0 = v0;
                *(float2*)p1 = v1;
            }
        }
    }
}

// ---------------- unified attention kernel -------------------------------------
// Blocks 0..7: hWa = h @ WaTtop^T + ba (fp16 GEMM), then release g_flag.
// Blocks 8..:  mask-compacted att GEMM with in-kernel fp32->fp16 enc conversion;
//              epilogue spins on g_flag, then att[b,s] = v . tanh(row + hWa[b,:]).
#define A32_STRIDE 144
#define ST_A32 (128 * A32_STRIDE)          // 18432
#define ATT_A16   0
#define ATT_A32_0 10240
#define ATT_B16_0 (ATT_A32_0 + 3 * ST_A32) // 65536
#define ATT_TOT   (ATT_B16_0 + 3 * ST_B)   // 126976

__global__ __launch_bounds__(256, 1)
void att_gemm(const float* __restrict__ Aenc, const __half* __restrict__ Bm,
              __half* __restrict__ enc_h,
              const __half* __restrict__ h_h, const __half* __restrict__ WaTtop,
              const float* __restrict__ ba, float* __restrict__ hWa,
              int* __restrict__ flagp,
              const float* __restrict__ vvec, float* __restrict__ att,
              const int* __restrict__ idxp, const int* __restrict__ cntp) {
    extern __shared__ char smem[];
    const uint32_t sbase = smem_u32(smem);
    const int K = Hq;                       // 256

    const int tid  = threadIdx.x;
    const int lane = tid & 31;
    const int warp = tid >> 5;
    const int wm = (warp >> 2) * 64;
    const int wn = (warp & 3) * 64;
    const int lq = lane >> 2;
    const int lr = lane & 3;

    // common ldmatrix per-lane offsets (80-byte row stride layout)
    const int rin = lane & 7;
    uint32_t a_l[4], b_l[4];
    {
        const int r8   = (lane >> 3) & 1;
        const int kh_a = (lane >> 4) & 1;
        const int n8   = (lane >> 4) & 1;
        const int kh_b = (lane >> 3) & 1;
#pragma unroll
        for (int mf = 0; mf < 4; mf++)
            a_l[mf] = (uint32_t)((wm + mf * 16 + r8 * 8 + rin) * 80 + kh_a * 16);
#pragma unroll
        for (int p2 = 0; p2 < 4; p2++)
            b_l[p2] = (uint32_t)((wn + p2 * 16 + n8 * 8 + rin) * 80 + kh_b * 16);
    }

    float acc[4][8][4];
#pragma unroll
    for (int i = 0; i < 4; i++)
#pragma unroll
        for (int j = 0; j < 8; j++)
#pragma unroll
            for (int k = 0; k < 4; k++) acc[i][j][k] = 0.0f;

    if (blockIdx.x < 8) {
        // ---------- hWa producer branch ----------
        const int bm = blockIdx.x * 128;

#define HISSUE(c)                                                           \
    do {                                                                    \
        const int kc = (c) * 32;                                            \
        const uint32_t sa0 = sbase + ((c) % 3) * STG_SZ;                    \
        const uint32_t sb0 = sa0 + ST_A;                                    \
        _Pragma("unroll")                                                   \
        for (int l = 0; l < 2; l++) {                                       \
            int q = tid + l * 256;                                          \
            int row = q >> 2, seg = q & 3;                                  \
            CPA16(sa0 + row * 80 + seg * 16,                                \
                  h_h + (size_t)(bm + row) * K + kc + seg * 8, true);       \
        }                                                                   \
        _Pragma("unroll")                                                   \
        for (int l = 0; l < 4; l++) {                                       \
            int q = tid + l * 256;                                          \
            int row = q >> 2, seg = q & 3;                                  \
            CPA16(sb0 + row * 80 + seg * 16,                                \
                  WaTtop + (size_t)row * K + kc + seg * 8, true);           \
        }                                                                   \
    } while (0)

        HISSUE(0); CPA_COMMIT();
        HISSUE(1); CPA_COMMIT();
        for (int c = 0; c < 8; c++) {
            CPA_WAIT1();
            __syncthreads();
            if (c + 2 < 8) HISSUE(c + 2);
            CPA_COMMIT();

            const uint32_t aA = sbase + (c % 3) * STG_SZ;
            const uint32_t aB = aA + ST_A;
#pragma unroll
            for (int ks = 0; ks < 2; ks++) {
                uint32_t bf[8][2];
#pragma unroll
                for (int p2 = 0; p2 < 4; p2++)
                    LDMX4(bf[2 * p2][0], bf[2 * p2][1], bf[2 * p2 + 1][0], bf[2 * p2 + 1][1],
                          aB + b_l[p2] + ks * 32);
#pragma unroll
                for (int mf = 0; mf < 4; mf++) {
                    uint32_t a0, a1, a2, a3;
                    LDMX4(a0, a1, a2, a3, aA + a_l[mf] + ks * 32);
#pragma unroll
                    for (int nf = 0; nf < 8; nf++)
                        mma_fp16(acc[mf][nf], a0, a1, a2, a3, bf[nf][0], bf[nf][1]);
                }
            }
        }
#undef HISSUE

#pragma unroll
        for (int mf = 0; mf < 4; mf++) {
            int r0 = bm + wm + mf * 16 + lq;
#pragma unroll
            for (int nf = 0; nf < 8; nf++) {
                int col = wn + nf * 8 + lr * 2;
                float b0 = ba[col], b1 = ba[col + 1];
                *(float2*)(hWa + (size_t)r0 * Hq + col) =
                    make_float2(acc[mf][nf][0] + b0, acc[mf][nf][1] + b1);
                *(float2*)(hWa + (size_t)(r0 + 8) * Hq + col) =
                    make_float2(acc[mf][nf][2] + b0, acc[mf][nf][3] + b1);
            }
        }
        __threadfence();
        __syncthreads();
        if (tid == 0) atomicAdd(flagp, 1);
        return;
    }

    // ---------- att consumer branch ----------
    const int bm = (blockIdx.x - 8) * 128;

    __shared__ float rowsum[128];
    __shared__ int   sidx[128];

    const int cnt_v = *cntp;
    if (bm >= cnt_v) return;
    if (tid < 128) {
        int g = bm + tid;
        sidx[tid] = (g < cnt_v) ? idxp[g] : idxp[0];
        rowsum[tid] = 0.0f;
    }
    __syncthreads();

    size_t arow_off[4];
#pragma unroll
    for (int l = 0; l < 4; l++) {
        int q = tid + l * 256;
        arow_off[l] = (size_t)sidx[q >> 3] * K;
    }
    const int crow = tid >> 1;
    const int chh  = tid & 1;
    const size_t grow_off = (size_t)sidx[crow] * K;

    const int nch = K / 32;                 // 8

#define AISSUE(c)                                                           \
    do {                                                                    \
        const int kc = (c) * 32;                                            \
        const uint32_t a32 = sbase + ATT_A32_0 + ((c) % 3) * ST_A32;        \
        const uint32_t b16 = sbase + ATT_B16_0 + ((c) % 3) * ST_B;          \
        _Pragma("unroll")                                                   \
        for (int l = 0; l < 4; l++) {                                       \
            int q = tid + l * 256;                                          \
            int row = q >> 3, seg = q & 7;                                  \
            CPA16(a32 + row * A32_STRIDE + seg * 16,                        \
                  Aenc + arow_off[l] + kc + seg * 4, true);                 \
        }                                                                   \
        _Pragma("unroll")                                                   \
        for (int l = 0; l < 4; l++) {                                       \
            int q = tid + l * 256;                                          \
            int row = q >> 2, seg = q & 3;                                  \
            CPA16(b16 + row * 80 + seg * 16,                                \
                  Bm + (size_t)row * K + kc + seg * 8, true);               \
        }                                                                   \
    } while (0)

    AISSUE(0); CPA_COMMIT();
    AISSUE(1); CPA_COMMIT();

    for (int c = 0; c < nch; c++) {
        CPA_WAIT1();
        __syncthreads();
        if (c + 2 < nch) AISSUE(c + 2);
        CPA_COMMIT();

        // convert this chunk's A: fp32 stage -> fp16 operand (+ enc_h store)
        {
            const int kc = c * 32;
            const char* src = smem + ATT_A32_0 + (c % 3) * ST_A32
                              + crow * A32_STRIDE + chh * 64;
            float4 f0 = *(const float4*)(src);
            float4 f1 = *(const float4*)(src + 16);
            float4 f2 = *(const float4*)(src + 32);
            float4 f3 = *(const float4*)(src + 48);
            uint4 h0, h1;
            h0.x = f2h2(f0.x, f0.y); h0.y = f2h2(f0.z, f0.w);
            h0.z = f2h2(f1.x, f1.y); h0.w = f2h2(f1.z, f1.w);
            h1.x = f2h2(f2.x, f2.y); h1.y = f2h2(f2.z, f2.w);
            h1.z = f2h2(f3.x, f3.y); h1.w = f2h2(f3.z, f3.w);
            char* dst = smem + ATT_A16 + crow * 80 + chh * 32;
            *(uint4*)(dst) = h0;
            *(uint4*)(dst + 16) = h1;
            __half* gdst = enc_h + grow_off + kc + chh * 16;
            *(uint4*)(gdst) = h0;
            *(uint4*)((char*)gdst + 16) = h1;
        }
        __syncthreads();

        const uint32_t aA = sbase + ATT_A16;
        const uint32_t aB = sbase + ATT_B16_0 + (c % 3) * ST_B;

#pragma unroll
        for (int ks = 0; ks < 2; ks++) {
            uint32_t bf[8][2];
#pragma unroll
            for (int p2 = 0; p2 < 4; p2++)
                LDMX4(bf[2 * p2][0], bf[2 * p2][1], bf[2 * p2 + 1][0], bf[2 * p2 + 1][1],
                      aB + b_l[p2] + ks * 32);
#pragma unroll
            for (int mf = 0; mf < 4; mf++) {
                uint32_t a0, a1, a2, a3;
                LDMX4(a0, a1, a2, a3, aA + a_l[mf] + ks * 32);
#pragma unroll
                for (int nf = 0; nf < 8; nf++)
                    mma_fp16(acc[mf][nf], a0, a1, a2, a3, bf[nf][0], bf[nf][1]);
            }
        }
    }
#undef AISSUE

    // wait for hWa producers (8 wave-1-resident CTAs; finish ~13us into kernel)
    if (tid == 0) {
        while (atomicAdd(flagp, 0) < 8) { }
    }
    __syncthreads();

    // epilogue: att[b,s] = v . tanh(row + hWa[b,:])
#pragma unroll
    for (int mf = 0; mf < 4; mf++) {
        int l0 = wm + mf * 16 + lq;
        int b0 = sidx[l0] & (Bq - 1);
        int b1 = sidx[l0 + 8] & (Bq - 1);
        float p0 = 0.0f, p1 = 0.0f;
#pragma unroll
        for (int nf = 0; nf < 8; nf++) {
#pragma unroll
            for (int c2 = 0; c2 < 2; c2++) {
                int col = wn + nf * 8 + lr * 2 + c2;
                float vv = vvec[col];
                p0 += tanhf(acc[mf][nf][c2]     + __ldcg(&hWa[b0 * Hq + col])) * vv;
                p1 += tanhf(acc[mf][nf][2 + c2] + __ldcg(&hWa[b1 * Hq + col])) * vv;
            }
        }
        p0 += __shfl_xor_sync(0xffffffffu, p0, 1);
        p0 += __shfl_xor_sync(0xffffffffu, p0, 2);
        p1 += __shfl_xor_sync(0xffffffffu, p1, 1);
        p1 += __shfl_xor_sync(0xffffffffu, p1, 2);
        if (lr == 0) {
            atomicAdd(&rowsum[l0], p0);
            atomicAdd(&rowsum[l0 + 8], p1);
        }
    }
    __syncthreads();
    if (tid < 128 && (bm + tid) < cnt_v) {
        int row = sidx[tid];               // = s*Bq + b
        int s = row >> 10;
        int b = row & (Bq - 1);
        att[b * Sq + s] = rowsum[tid];
    }
}

// ---------------- prep: hidden fp32->fp16 + zero counters/flag -----------------
__global__ void prep_kernel(const float* __restrict__ hidden,
                            __half* __restrict__ h_h,
                            int* __restrict__ cnt, int* __restrict__ flag) {
    int i = blockIdx.x * 256 + threadIdx.x;       // exactly 65536 threads
    float4 f = ((const float4*)hidden)[i];
    uint2 u;
    u.x = f2h2(f.x, f.y);
    u.y = f2h2(f.z, f.w);
    ((uint2*)h_h)[i] = u;
    if (i < 4) cnt[i] = 0;
    if (i == 4) *flag = 0;
}

// ---------------- emb gather -> rnn_in[:, 0:128] (fp16) ------------------------
__global__ void emb_gather(const float* __restrict__ emb,
                           const int* __restrict__ loc,
                           __half* __restrict__ rnn_h) {
    int b = blockIdx.x;
    int t = threadIdx.x;                           // 32 threads
    float4 f = ((const float4*)emb)[(size_t)loc[b] * 32 + t];
    uint2 u;
    u.x = f2h2(f.x, f.y);
    u.y = f2h2(f.z, f.w);
    ((uint2*)(rnn_h + (size_t)b * (Eq + Hq)))[t] = u;
}

// ---------------- mask stream-compaction (single list) -------------------------
__global__ void scan_mask(const int* __restrict__ mask,
                          int* __restrict__ idx, int* __restrict__ cnt,
                          float* __restrict__ att) {
    int i = blockIdx.x * 256 + threadIdx.x;       // row id = s*Bq + b
    int s = i >> 10;
    int b = i & (Bq - 1);
    bool keep = mask[b * Sq + s] != 0;
    if (!keep) att[b * Sq + s] = -1000000.0f;

    int lane = threadIdx.x & 31, w = threadIdx.x >> 5;
    unsigned bal = __ballot_sync(0xffffffffu, keep);
    int wcnt = __popc(bal);

    __shared__ int wbase[8];
    __shared__ int btot;
    __shared__ int bbase;
    if (threadIdx.x == 0) btot = 0;
    __syncthreads();
    if (lane == 0) wbase[w] = atomicAdd(&btot, wcnt);
    __syncthreads();
    if (threadIdx.x == 0) bbase = atomicAdd(&cnt[0], btot);
    __syncthreads();
    if (keep) {
        int off = bbase + wbase[w] + __popc(bal & ((1u << lane) - 1u));
        idx[off] = i;
    }
}

// ---------------- fp32 -> fp16 convert (n % 4 == 0) ----------------------------
__global__ void f32to16(const float* __restrict__ in, __half* __restrict__ out, int n4) {
    int i = blockIdx.x * 256 + threadIdx.x;
    if (i < n4) {
        float4 f = ((const float4*)in)[i];
        uint2 u;
        u.x = f2h2(f.x, f.y);
        u.y = f2h2(f.z, f.w);
        ((uint2*)out)[i] = u;
    }
}

// ---------------- Wa transpose -> half -----------------------------------------
__global__ void transpose_wa(const float* __restrict__ Wa,
                             __half* __restrict__ top, __half* __restrict__ bot) {
    int idx = blockIdx.x * 256 + threadIdx.x;
    if (idx >= 2 * Hq * Hq) return;
    int k = idx / Hq;
    int n = idx - k * Hq;
    __half val = __float2half_rn(Wa[k * Hq + n]);
    if (k < Hq) top[n * Hq + k] = val;
    else        bot[n * Hq + (k - Hq)] = val;
}

// ---------------- fused softmax + weighted sum -> rnn_in ctx -------------------
__global__ __launch_bounds__(256)
void softmax_weighted(const float* __restrict__ att,
                      const __half* __restrict__ enc_h,
                      __half* __restrict__ rnn_h) {
    int b = blockIdx.x;
    int t = threadIdx.x;
    __shared__ float satt[Sq];
    __shared__ float red[8];
    __shared__ float4 red4[256];

    float x = (t < Sq) ? att[b * Sq + t] : -3.4e38f;
    int lane = t & 31, w = t >> 5;

    float m = x;
    for (int o = 16; o > 0; o >>= 1) m = fmaxf(m, __shfl_down_sync(0xffffffffu, m, o));
    if (lane == 0) red[w] = m;
    __syncthreads();
    if (t == 0) {
        float mm = red[0];
        for (int i = 1; i < 8; i++) mm = fmaxf(mm, red[i]);
        red[0] = mm;
    }
    __syncthreads();
    m = red[0];
    __syncthreads();

    float e = (t < Sq) ? expf(x - m) : 0.0f;
    float s = e;
    for (int o = 16; o > 0; o >>= 1) s += __shfl_down_sync(0xffffffffu, s, o);
    if (lane == 0) red[w] = s;
    __syncthreads();
    if (t == 0) {
        float ss = 0.0f;
        for (int i = 0; i < 8; i++) ss += red[i];
        red[0] = ss;
    }
    __syncthreads();
    float denom = red[0];
    if (t < Sq) satt[t] = e / denom;
    __syncthreads();

    int sp = t >> 6;
    int hq = t & 63;
    const uint2* enc2 = (const uint2*)enc_h;
    float4 acc = make_float4(0.f, 0.f, 0.f, 0.f);
    for (int si = sp; si < Sq; si += 4) {
        float ww = satt[si];
        uint2 u = enc2[((size_t)si * Bq + b) * 64 + hq];
        float2 f0 = __half22float2(*(__half2*)&u.x);
        float2 f1 = __half22float2(*(__half2*)&u.y);
        acc.x += ww * f0.x; acc.y += ww * f0.y; acc.z += ww * f1.x; acc.w += ww * f1.y;
    }
    red4[t] = acc;
    __syncthreads();

    uint2* rnn2 = (uint2*)(rnn_h + (size_t)b * (Eq + Hq));
    if (t < 64) {
        float4 a0 = red4[t], a1 = red4[64 + t], a2 = red4[128 + t], a3 = red4[192 + t];
        uint2 u;
        u.x = f2h2(a0.x + a1.x + a2.x + a3.x, a0.y + a1.y + a2.y + a3.y);
        u.y = f2h2(a0.z + a1.z + a2.z + a3.z, a0.w + a1.w + a2.w + a3.w);
        rnn2[32 + t] = u;
    }
}

// ---------------- GRU gates ----------------------------------------------------
__global__ void gru_kernel(const float* __restrict__ gi, const float* __restrict__ gh,
                           const float* __restrict__ h,
                           __half* __restrict__ hnew_h, float* __restrict__ out_h) {
    int b = blockIdx.x;
    int j = threadIdx.x;
    float ir = gi[b * 768 + j];
    float iz = gi[b * 768 + 256 + j];
    float in = gi[b * 768 + 512 + j];
    float hr = gh[b * 768 + j];
    float hz = gh[b * 768 + 256 + j];
    float hn = gh[b * 768 + 512 + j];
    float r = 1.0f / (1.0f + expf(-(ir + hr)));
    float z = 1.0f / (1.0f + expf(-(iz + hz)));
    float n = tanhf(in + r * hn);
    float hv = h[b * Hq + j];
    float hnv = (1.0f - z) * n + z * hv;
    hnew_h[b * Hq + j] = __float2half_rn(hnv);
    out_h[b * Hq + j] = hnv;
}

// ---------------- launch -------------------------------------------------------
extern "C" void kernel_launch(void* const* d_in, const int* in_sizes, int n_in,
                              void* d_out, int out_size) {
    const int*   input_loc = (const int*)d_in[0];
    const float* hidden    = (const float*)d_in[1];
    const float* enc       = (const float*)d_in[2];
    const int*   mask      = (const int*)d_in[3];
    const float* emb       = (const float*)d_in[4];
    const float* Wa        = (const float*)d_in[5];
    const float* ba        = (const float*)d_in[6];
    const float* v         = (const float*)d_in[7];
    const float* W_ih      = (const float*)d_in[8];
    const float* W_hh      = (const float*)d_in[9];
    const float* b_ih      = (const float*)d_in[10];
    const float* b_hh      = (const float*)d_in[11];
    const float* W_out     = (const float*)d_in[12];
    const float* b_out     = (const float*)d_in[13];
    float* out = (float*)d_out;
    float* out_pred = out;
    float* out_h    = out + (size_t)Bq * Vq;

    __half *enc_h, *Wout_h, *WaTtop_h, *WaTbot_h, *h_h, *Wih_h, *Whh_h, *rnnin_h, *hnew_h;
    float  *hWa, *att, *gi, *gh;
    int    *idx, *cnt, *flag;
    cudaGetSymbolAddress((void**)&enc_h,    g_enc_h);
    cudaGetSymbolAddress((void**)&Wout_h,   g_Wout_h);
    cudaGetSymbolAddress((void**)&WaTtop_h, g_WaTtop_h);
    cudaGetSymbolAddress((void**)&WaTbot_h, g_WaTbot_h);
    cudaGetSymbolAddress((void**)&h_h,      g_h_h);
    cudaGetSymbolAddress((void**)&Wih_h,    g_Wih_h);
    cudaGetSymbolAddress((void**)&Whh_h,    g_Whh_h);
    cudaGetSymbolAddress((void**)&rnnin_h,  g_rnnin_h);
    cudaGetSymbolAddress((void**)&hnew_h,   g_hnew_h);
    cudaGetSymbolAddress((void**)&hWa,      g_hWa);
    cudaGetSymbolAddress((void**)&att,      g_att);
    cudaGetSymbolAddress((void**)&gi,       g_gi);
    cudaGetSymbolAddress((void**)&gh,       g_gh);
    cudaGetSymbolAddress((void**)&idx,      g_idx);
    cudaGetSymbolAddress((void**)&cnt,      g_cnt);
    cudaGetSymbolAddress((void**)&flag,     g_flag);

    cudaFuncSetAttribute(mma_gemm, cudaFuncAttributeMaxDynamicSharedMemorySize, GTOT);
    cudaFuncSetAttribute(att_gemm, cudaFuncAttributeMaxDynamicSharedMemorySize, ATT_TOT);

    static cudaStream_t s2 = nullptr;
    static cudaEvent_t evFork = nullptr, evPre = nullptr, evGiE = nullptr;
    static cudaEvent_t evGh = nullptr, evW = nullptr;
    if (!s2) {
        cudaStreamCreateWithFlags(&s2, cudaStreamNonBlocking);
        cudaEventCreateWithFlags(&evFork, cudaEventDisableTiming);
        cudaEventCreateWithFlags(&evPre,  cudaEventDisableTiming);
        cudaEventCreateWithFlags(&evGiE,  cudaEventDisableTiming);
        cudaEventCreateWithFlags(&evGh,   cudaEventDisableTiming);
        cudaEventCreateWithFlags(&evW,    cudaEventDisableTiming);
    }

    // fork
    cudaEventRecord(evFork, 0);
    cudaStreamWaitEvent(s2, evFork, 0);

    // s0: hidden conv + zero cnt/flag; emb gather; Wa transpose; mask compaction
    prep_kernel<<<(Bq * Hq / 4) / 256, 256>>>(hidden, h_h, cnt, flag);
    emb_gather<<<Bq, 32>>>(emb, input_loc, rnnin_h);
    cudaEventRecord(evPre, 0);
    transpose_wa<<<512, 256>>>(Wa, WaTtop_h, WaTbot_h);
    scan_mask<<<(Sq * Bq) / 256, 256>>>(mask, idx, cnt, att);

    // s2: W_ih conv; gi_early (xh part, K=128); W_hh conv; gh; W_out conv
    {
        int n4 = (3 * Hq * (Eq + Hq)) / 4;
        f32to16<<<(n4 + 255) / 256, 256, 0, s2>>>(W_ih, Wih_h, n4);
        cudaStreamWaitEvent(s2, evPre, 0);
        mma_gemm<<<dim3(Bq / 128, 3), 256, GTOT, s2>>>(
            rnnin_h, Wih_h, b_ih, gi, Bq, 3 * Hq, Eq, Eq + Hq, Eq + Hq, 0);
        cudaEventRecord(evGiE, s2);
        n4 = (3 * Hq * Hq) / 4;
        f32to16<<<(n4 + 255) / 256, 256, 0, s2>>>(W_hh, Whh_h, n4);
        mma_gemm<<<dim3(Bq / 128, 3), 256, GTOT, s2>>>(
            h_h, Whh_h, b_hh, gh, Bq, 3 * Hq, Hq, Hq, Hq, 0);
        cudaEventRecord(evGh, s2);
        n4 = (Vq * Hq) / 4;
        f32to16<<<(n4 + 255) / 256, 256, 0, s2>>>(W_out, Wout_h, n4);
        cudaEventRecord(evW, s2);
    }

    // s0: unified attention kernel (8 hWa producer CTAs + 1600 att CTAs)
    att_gemm<<<dim3((Sq * Bq) / 128 + 8, 1), 256, ATT_TOT>>>(
        enc, WaTbot_h, enc_h, h_h, WaTtop_h, ba, hWa, flag,
        v, att, idx, cnt);

    // softmax + weighted context
    softmax_weighted<<<Bq, 256>>>(att, enc_h, rnnin_h);

    // gi += ctx @ W_ih[:,128:]^T (join gi_early)
    cudaStreamWaitEvent(0, evGiE, 0);
    mma_gemm<<<dim3(Bq / 128, 3), 256, GTOT>>>(
        rnnin_h + Eq, Wih_h + Eq, nullptr, gi, Bq, 3 * Hq, Hq,
        Eq + Hq, Eq + Hq, 1);

    // GRU gates (join gh)
    cudaStreamWaitEvent(0, evGh, 0);
    gru_kernel<<<Bq, Hq>>>(gi, gh, hidden, hnew_h, out_h);

    // pred = h_new @ W_out^T + b_out (join W_out conversion)
    cudaStreamWaitEvent(0, evW, 0);
    mma_gemm<<<dim3(Bq / 128, (Vq + 255) / 256), 256, GTOT>>>(
        hnew_h, Wout_h, b_out, out_pred, Bq, Vq, Hq, Hq, Hq, 0);
}